// round 12
// baseline (speedup 1.0000x reference)
#include <cuda_runtime.h>
#include <cuda_fp16.h>
#include <cstdint>

#define OUT_F 2048
#define IN_F  2048
#define NNZ   209715
#define T_TOK 16384

// ---------------------------------------------------------------------------
// Scratch + sync flags.
// ---------------------------------------------------------------------------
__device__ __half g_Wh[OUT_F * IN_F];           //  8 MB
__device__ __half g_Xh[(size_t)T_TOK * IN_F];   // 64 MB
__device__ unsigned g_dq_done;                  // dequant blocks finished
__device__ unsigned g_sc_done;                  // scatter blocks finished
__device__ unsigned g_cvt_cnt[128];             // cvt blocks finished per m-block
__device__ unsigned g_fin;                      // gemm CTAs finished

__device__ __forceinline__ uint32_t smem_u32(const void* p) {
    uint32_t a;
    asm("{ .reg .u64 t; cvta.to.shared.u64 t, %1; cvt.u32.u64 %0, t; }"
        : "=r"(a) : "l"(p));
    return a;
}

#define CP_ASYNC16(dst, src) \
    asm volatile("cp.async.cg.shared.global [%0], [%1], 16;" \
                 :: "r"((uint32_t)(dst)), "l"(src) : "memory")
#define CP_COMMIT() asm volatile("cp.async.commit_group;" ::: "memory")
#define CP_WAITN(n) asm volatile("cp.async.wait_group %0;" :: "n"(n) : "memory")

#define SWZ(o) ((o) ^ (((o) >> 3) & 0x70))

__device__ __forceinline__ void ldmatrix_x4(uint32_t* r, uint32_t addr) {
    asm volatile("ldmatrix.sync.aligned.m8n8.x4.shared.b16 {%0,%1,%2,%3}, [%4];"
                 : "=r"(r[0]), "=r"(r[1]), "=r"(r[2]), "=r"(r[3]) : "r"(addr));
}

__device__ __forceinline__ void mma_16816(float* c, const uint32_t* a,
                                          const uint32_t* b) {
    asm volatile(
        "mma.sync.aligned.m16n8k16.row.col.f32.f16.f16.f32 "
        "{%0,%1,%2,%3}, {%4,%5,%6,%7}, {%8,%9}, {%0,%1,%2,%3};"
        : "+f"(c[0]), "+f"(c[1]), "+f"(c[2]), "+f"(c[3])
        : "r"(a[0]), "r"(a[1]), "r"(a[2]), "r"(a[3]), "r"(b[0]), "r"(b[1]));
}

// ---------------------------------------------------------------------------
// Block-class sizes (all blocks 128 threads).
// ---------------------------------------------------------------------------
#define DQB   4096     // 524288 int4-groups / 128
#define SCB   1639     // ceil(NNZ / 128)
#define CVB   8192     // 8388608 float4 / 1024 per block
#define GEMXB 16       // n-blocks
#define GEMYB 128      // m-blocks
#define GEMMB (GEMXB * GEMYB)                 // 2048
#define CV_PER_MB 64   // cvt blocks per gemm m-block (8192/128)

// GEMM config (R9 best: 128x128, BK=64, 3-stage, 4 warps of 64x64).
#define MT 128
#define NT 128
#define BK 64
#define NSTAGE 3
#define STAGE_BYTES 32768u
#define A_OFF(s) ((s) * STAGE_BYTES)
#define B_OFF(s) (A_OFF(s) + 16384u)
#define GEMM_SMEM (NSTAGE * STAGE_BYTES)      // 98304

__device__ __forceinline__ void load_stage(uint32_t sb, int tid,
                                           const __half* Xb, const __half* Wb,
                                           int k0, int s) {
    #pragma unroll
    for (int j = 0; j < 8; j++) {
        int item = tid + j * 128;
        int row = item >> 3, ck = item & 7;
        CP_ASYNC16(sb + A_OFF(s) + SWZ(row * 128 + ck * 16),
                   Xb + (size_t)row * IN_F + k0 + ck * 8);
    }
    #pragma unroll
    for (int j = 0; j < 8; j++) {
        int item = tid + j * 128;
        int row = item >> 3, ck = item & 7;
        CP_ASYNC16(sb + B_OFF(s) + SWZ(row * 128 + ck * 16),
                   Wb + (size_t)row * IN_F + k0 + ck * 8);
    }
    CP_COMMIT();
}

__device__ __forceinline__ void load_frags(uint32_t sA, uint32_t sB,
                                           int wm, int wn, int lane, int kslot,
                                           uint32_t af[4][4], uint32_t bf[8][2]) {
    const int ckb = kslot * 2;
    #pragma unroll
    for (int mt = 0; mt < 4; mt++) {
        int row = wm + mt * 16 + (lane & 7) + ((lane >> 3) & 1) * 8;
        int ck  = ckb + ((lane >> 4) & 1);
        ldmatrix_x4(af[mt], sA + SWZ(row * 128 + ck * 16));
    }
    #pragma unroll
    for (int np = 0; np < 4; np++) {
        int sel = lane >> 3;
        int row = wn + np * 16 + (sel >> 1) * 8 + (lane & 7);
        int ck  = ckb + (sel & 1);
        uint32_t r[4];
        ldmatrix_x4(r, sB + SWZ(row * 128 + ck * 16));
        bf[np * 2 + 0][0] = r[0]; bf[np * 2 + 0][1] = r[1];
        bf[np * 2 + 1][0] = r[2]; bf[np * 2 + 1][1] = r[3];
    }
}

// ---------------------------------------------------------------------------
// ONE kernel: [dequant | scatter | cvt | gemm].  Classes only wait on
// strictly-earlier dispatch classes -> deadlock-free.  Last gemm CTA resets
// all flags so every graph replay starts from the same state.
// ---------------------------------------------------------------------------
__global__ __launch_bounds__(128, 2) void fused_kernel(
    const int*   __restrict__ packed,
    const float* __restrict__ scales,
    const float* __restrict__ x,
    const float* __restrict__ vals,
    const int*   __restrict__ rows,
    const int*   __restrict__ cols,
    float*       __restrict__ C) {
    extern __shared__ char smem[];
    const int bid = blockIdx.x;
    const int tid = threadIdx.x;

    if (bid < DQB) {
        // ---- dequant: one int4-group (8 halfs) per thread ----
        int idx = bid * 128 + tid;
        int o = idx >> 8;                                  // / (IN_F/8)
        int4 v = reinterpret_cast<const int4*>(packed)[idx];
        float s = scales[o];
        __half2 h[4];
        h[0] = __floats2half2_rn((float)((v.x & 0xF) - 8) * s,
                                 (float)(((v.x >> 4) & 0xF) - 8) * s);
        h[1] = __floats2half2_rn((float)((v.y & 0xF) - 8) * s,
                                 (float)(((v.y >> 4) & 0xF) - 8) * s);
        h[2] = __floats2half2_rn((float)((v.z & 0xF) - 8) * s,
                                 (float)(((v.z >> 4) & 0xF) - 8) * s);
        h[3] = __floats2half2_rn((float)((v.w & 0xF) - 8) * s,
                                 (float)(((v.w >> 4) & 0xF) - 8) * s);
        reinterpret_cast<uint4*>(g_Wh)[idx] = *reinterpret_cast<uint4*>(h);
        __syncthreads();
        if (tid == 0) { __threadfence(); atomicAdd(&g_dq_done, 1u); }
        return;
    }
    if (bid < DQB + SCB) {
        // ---- scatter: wait for dequant, atomicAdd residuals ----
        if (tid == 0) {
            volatile unsigned* f = &g_dq_done;
            while (*f < DQB) { asm volatile("nanosleep.u32 64;"); }
        }
        __syncthreads();
        __threadfence();
        int i = (bid - DQB) * 128 + tid;
        if (i < NNZ)
            atomicAdd(&g_Wh[(size_t)rows[i] * IN_F + cols[i]],
                      __float2half(vals[i]));
        __syncthreads();
        if (tid == 0) { __threadfence(); atomicAdd(&g_sc_done, 1u); }
        return;
    }
    if (bid < DQB + SCB + CVB) {
        // ---- cvt: 1024 float4 per block (8 per thread) ----
        int cb = bid - DQB - SCB;
        int base = cb * 1024;
        #pragma unroll
        for (int j = 0; j < 8; j++) {
            int i = base + tid + j * 128;
            float4 v = reinterpret_cast<const float4*>(x)[i];
            reinterpret_cast<__half2*>(g_Xh)[2 * i]     = __floats2half2_rn(v.x, v.y);
            reinterpret_cast<__half2*>(g_Xh)[2 * i + 1] = __floats2half2_rn(v.z, v.w);
        }
        __syncthreads();
        if (tid == 0) { __threadfence(); atomicAdd(&g_cvt_cnt[cb >> 6], 1u); }
        return;
    }

    // ---- gemm CTA ----
    const int g   = bid - DQB - SCB - CVB;
    const int n0  = (g & (GEMXB - 1)) * NT;
    const int by  = g >> 4;
    const int m0  = by * MT;

    // Wait for W (scatter) and this m-block's X conversion.
    if (tid == 0) {
        volatile unsigned* fs = &g_sc_done;
        while (*fs < SCB) { asm volatile("nanosleep.u32 64;"); }
        volatile unsigned* fc = &g_cvt_cnt[by];
        while (*fc < CV_PER_MB) { asm volatile("nanosleep.u32 64;"); }
    }
    __syncthreads();
    __threadfence();

    const uint32_t sb = smem_u32(smem);
    const int wid  = tid >> 5;
    const int lane = tid & 31;
    const int wm = (wid & 1) * 64;
    const int wn = (wid >> 1) * 64;

    const __half* Xb = g_Xh + (size_t)m0 * IN_F;
    const __half* Wb = g_Wh + (size_t)n0 * IN_F;

    float acc[4][8][4];
    #pragma unroll
    for (int i = 0; i < 4; i++)
        #pragma unroll
        for (int j = 0; j < 8; j++)
            #pragma unroll
            for (int q = 0; q < 4; q++) acc[i][j][q] = 0.0f;

    load_stage(sb, tid, Xb, Wb, 0, 0);
    load_stage(sb, tid, Xb, Wb, BK, 1);

    uint32_t af[2][4][4];
    uint32_t bf[2][8][2];

    const int NIT = IN_F / BK;   // 32
    for (int k = 0; k < NIT; k++) {
        if (k + 1 < NIT) CP_WAITN(1); else CP_WAITN(0);
        __syncthreads();

        if (k + 2 < NIT)
            load_stage(sb, tid, Xb, Wb, (k + 2) * BK, (k + 2) % NSTAGE);

        const int st = k % NSTAGE;
        const uint32_t sA = sb + A_OFF(st);
        const uint32_t sB = sb + B_OFF(st);

        load_frags(sA, sB, wm, wn, lane, 0, af[0], bf[0]);

        #pragma unroll
        for (int ks = 0; ks < BK / 16; ks++) {
            const int cur = ks & 1;
            if (ks + 1 < BK / 16)
                load_frags(sA, sB, wm, wn, lane, ks + 1,
                           af[cur ^ 1], bf[cur ^ 1]);
            #pragma unroll
            for (int mt = 0; mt < 4; mt++)
                #pragma unroll
                for (int nt = 0; nt < 8; nt++)
                    mma_16816(acc[mt][nt], af[cur][mt], bf[cur][nt]);
        }
    }

    #pragma unroll
    for (int mt = 0; mt < 4; mt++) {
        #pragma unroll
        for (int nt = 0; nt < 8; nt++) {
            int m = m0 + wm + mt * 16 + (lane >> 2);
            int n = n0 + wn + nt * 8 + (lane & 3) * 2;
            float2* p0 = reinterpret_cast<float2*>(C + (size_t)m * OUT_F + n);
            float2* p1 = reinterpret_cast<float2*>(C + (size_t)(m + 8) * OUT_F + n);
            *p0 = make_float2(acc[mt][nt][0], acc[mt][nt][1]);
            *p1 = make_float2(acc[mt][nt][2], acc[mt][nt][3]);
        }
    }

    // Completion: last gemm CTA resets all flags (all readers are done by
    // construction -> deterministic state for the next graph replay).
    __syncthreads();
    if (tid == 0) {
        unsigned old = atomicAdd(&g_fin, 1u);
        if (old == GEMMB - 1) {
            g_dq_done = 0;
            g_sc_done = 0;
            g_fin = 0;
            #pragma unroll
            for (int i = 0; i < 128; i++) g_cvt_cnt[i] = 0;
            __threadfence();
        }
    }
}

// ---------------------------------------------------------------------------
// Launch: ONE kernel.
// ---------------------------------------------------------------------------
extern "C" void kernel_launch(void* const* d_in, const int* in_sizes, int n_in,
                              void* d_out, int out_size) {
    const float* x      = (const float*)d_in[0];
    const int*   packed = (const int*)  d_in[1];
    const float* scales = (const float*)d_in[2];
    const float* o_vals = (const float*)d_in[3];
    const int*   o_rows = (const int*)  d_in[4];
    const int*   o_cols = (const int*)  d_in[5];
    float*       out    = (float*)d_out;

    cudaFuncSetAttribute(fused_kernel,
                         cudaFuncAttributeMaxDynamicSharedMemorySize, GEMM_SMEM);

    fused_kernel<<<DQB + SCB + CVB + GEMMB, 128, GEMM_SMEM>>>(
        packed, scales, x, o_vals, o_rows, o_cols, out);
}